// round 7
// baseline (speedup 1.0000x reference)
#include <cuda_runtime.h>

#define NN 60000
#define EE 240000
#define GG 512

// ---------------- scratch layout (floats) — dense per-array (R3 layout) ----------------
// X12  : N*12   padded input features (rebuilt by init each call)
// GC   : N*32   [g1(16) | c1(16)] per node (overwritten by post1)
// AGG1 : N*64   [a*x(12) | e0*x | e1*x | e2*x | 1*x (each 12) | pad 4]  (self-restoring zero)
// AGG2 : N*80   [a*g1(16) | e0*c1 | e1*c1 | e2*c1 | 1*c1 (each 16)]    (self-restoring zero)
// POOL : G*64   [g2-pool(32) | c2-pool(32)]                             (self-restoring zero)
constexpr int OFF_X12  = 0;
constexpr int OFF_GC   = OFF_X12 + NN * 12;
constexpr int OFF_AGG1 = OFF_GC  + NN * 32;
constexpr int OFF_AGG2 = OFF_AGG1 + NN * 64;
constexpr int OFF_POOL = OFF_AGG2 + NN * 80;
constexpr int SCRATCH_TOTAL = OFF_POOL + GG * 64;

__device__ __align__(16) float d_scratch[SCRATCH_TOTAL];

// ---------------- helpers ----------------
__device__ __forceinline__ void red_add_v4(float* addr, float4 v) {
    asm volatile("red.global.add.v4.f32 [%0], {%1, %2, %3, %4};"
                 :: "l"(addr), "f"(v.x), "f"(v.y), "f"(v.z), "f"(v.w)
                 : "memory");
}
__device__ __forceinline__ void red_add_f(float* addr, float v) {
    asm volatile("red.global.add.f32 [%0], %1;" :: "l"(addr), "f"(v) : "memory");
}

typedef unsigned long long ull;

__device__ __forceinline__ ull pk2(float lo, float hi) {
    ull r;
    asm("mov.b64 %0, {%1, %2};" : "=l"(r) : "f"(lo), "f"(hi));
    return r;
}
__device__ __forceinline__ void fma2(ull& acc, ull a, ull b) {
    asm("fma.rn.f32x2 %0, %1, %2, %0;" : "+l"(acc) : "l"(a), "l"(b));
}
__device__ __forceinline__ float2 upk(ull v) {
    float2 o;
    asm("mov.b64 {%0, %1}, %2;" : "=f"(o.x), "=f"(o.y) : "l"(v));
    return o;
}

// ---------------- init: build dense X12 only ----------------
__global__ void init_kernel(const float* __restrict__ x) {
    int i = blockIdx.x * blockDim.x + threadIdx.x;
    if (i >= NN * 3) return;
    int node = i / 3, p = i - node * 3;
    int f0 = p * 4;
    const float* xr = x + node * 10;
    float4 v;
    v.x = (f0 + 0 < 10) ? xr[f0 + 0] : 0.f;
    v.y = (f0 + 1 < 10) ? xr[f0 + 1] : 0.f;
    v.z = (f0 + 2 < 10) ? xr[f0 + 2] : 0.f;
    v.w = (f0 + 3 < 10) ? xr[f0 + 3] : 0.f;
    ((float4*)(d_scratch + OFF_X12))[node * 3 + p] = v;
}

// ---------------- pass1: scatter coeff*x12 into AGG1 (5 thr/edge) ----------------
__global__ void pass1_kernel(const int* __restrict__ ei,
                             const float* __restrict__ av,
                             const float* __restrict__ ef) {
    int t = blockIdx.x * blockDim.x + threadIdx.x;
    int edge = t / 5;
    int q = t - edge * 5;
    if (edge >= EE) return;
    int row = ei[edge];
    int col = ei[EE + edge];
    float coeff;
    if (q == 0)      coeff = av[edge];
    else if (q < 4)  coeff = ef[edge * 3 + (q - 1)];
    else             coeff = 1.f;
    const float4* xp = (const float4*)(d_scratch + OFF_X12 + col * 12);
    float* dst = d_scratch + OFF_AGG1 + row * 64 + q * 12;
#pragma unroll
    for (int k = 0; k < 3; k++) {
        float4 v = xp[k];
        red_add_v4(dst + k * 4,
                   make_float4(coeff * v.x, coeff * v.y, coeff * v.z, coeff * v.w));
    }
}

// ---------------- post1: staged contraction -> GC; re-zero AGG1 ----------------
__global__ __launch_bounds__(128) void post1_kernel(const float* __restrict__ Wg1,
                                                    const float* __restrict__ bg1,
                                                    const float* __restrict__ We1,
                                                    const float* __restrict__ be1,
                                                    const float* __restrict__ root1,
                                                    const float* __restrict__ bias1) {
    extern __shared__ float sA[];                 // [128][77]: agg(64) | x12(12) | pad
    __shared__ __align__(16) float sWg1[160];     // [f<10][o<16]
    __shared__ __align__(16) float sK[640];       // [s<4][f<10][o<16] (s=3 -> be1)
    __shared__ __align__(16) float sR[160];       // [f<10][o<16]
    __shared__ float sBg[16], sB1[16];
    int tid = threadIdx.x;
    int tb = blockIdx.x * 128;
    for (int i = tid; i < 160; i += 128) { sWg1[i] = Wg1[i]; sR[i] = root1[i]; }
    for (int i = tid; i < 640; i += 128) sK[i] = (i < 480) ? We1[i] : be1[i - 480];
    if (tid < 16) { sBg[tid] = bg1[tid]; sB1[tid] = bias1[tid]; }
    // stage AGG1 tile (coalesced float4) + immediately re-zero
    for (int i = tid; i < 2048; i += 128) {
        int node = i >> 4, k = (i & 15) * 4;
        float4 v = make_float4(0.f, 0.f, 0.f, 0.f);
        if (tb + node < NN) {
            float4* g = (float4*)(d_scratch + OFF_AGG1 + (tb + node) * 64 + k);
            v = *g;
            *g = make_float4(0.f, 0.f, 0.f, 0.f);
        }
        float* s = &sA[node * 77 + k];
        s[0] = v.x; s[1] = v.y; s[2] = v.z; s[3] = v.w;
    }
    // stage X12 tile (coalesced float4)
    for (int i = tid; i < 384; i += 128) {
        int node = i / 3, k = (i % 3) * 4;
        float4 v = make_float4(0.f, 0.f, 0.f, 0.f);
        if (tb + node < NN)
            v = *(const float4*)(d_scratch + OFF_X12 + (tb + node) * 12 + k);
        float* s = &sA[node * 77 + 64 + k];
        s[0] = v.x; s[1] = v.y; s[2] = v.z; s[3] = v.w;
    }
    __syncthreads();
    int node = tb + tid;
    ull ga[8], ca[8];
#pragma unroll
    for (int k = 0; k < 8; k++) {
        ga[k] = pk2(sBg[2 * k], sBg[2 * k + 1]);
        ca[k] = pk2(sB1[2 * k], sB1[2 * k + 1]);
    }
    const float* Ar = &sA[tid * 77];
    // gcn: q=0 slot
#pragma unroll
    for (int f = 0; f < 10; f++) {
        ull s = pk2(Ar[f], Ar[f]);
        const ulonglong2* w = (const ulonglong2*)&sWg1[f * 16];
#pragma unroll
        for (int k = 0; k < 4; k++) {
            ulonglong2 wp = w[k];
            fma2(ga[2 * k], s, wp.x);
            fma2(ga[2 * k + 1], s, wp.y);
        }
    }
    // ecc: q=1..4
#pragma unroll
    for (int q = 1; q < 5; q++) {
#pragma unroll
        for (int f = 0; f < 10; f++) {
            ull s = pk2(Ar[q * 12 + f], Ar[q * 12 + f]);
            const ulonglong2* w = (const ulonglong2*)&sK[(q - 1) * 160 + f * 16];
#pragma unroll
            for (int k = 0; k < 4; k++) {
                ulonglong2 wp = w[k];
                fma2(ca[2 * k], s, wp.x);
                fma2(ca[2 * k + 1], s, wp.y);
            }
        }
    }
    // root: x12
#pragma unroll
    for (int f = 0; f < 10; f++) {
        ull s = pk2(Ar[64 + f], Ar[64 + f]);
        const ulonglong2* w = (const ulonglong2*)&sR[f * 16];
#pragma unroll
        for (int k = 0; k < 4; k++) {
            ulonglong2 wp = w[k];
            fma2(ca[2 * k], s, wp.x);
            fma2(ca[2 * k + 1], s, wp.y);
        }
    }
    if (node < NN) {
        float4* o = (float4*)(d_scratch + OFF_GC + node * 32);
#pragma unroll
        for (int k = 0; k < 4; k++) {
            float2 a0 = upk(ga[2 * k]), a1 = upk(ga[2 * k + 1]);
            o[k] = make_float4(fmaxf(a0.x, 0.f), fmaxf(a0.y, 0.f),
                               fmaxf(a1.x, 0.f), fmaxf(a1.y, 0.f));
            float2 b0 = upk(ca[2 * k]), b1 = upk(ca[2 * k + 1]);
            o[4 + k] = make_float4(fmaxf(b0.x, 0.f), fmaxf(b0.y, 0.f),
                                   fmaxf(b1.x, 0.f), fmaxf(b1.y, 0.f));
        }
    }
}

// ---------------- pass2: scatter coeff*(g1|c1) into AGG2 (4 thr/edge) ----------------
__global__ void pass2_kernel(const int* __restrict__ ei,
                             const float* __restrict__ av,
                             const float* __restrict__ ef) {
    int t = blockIdx.x * blockDim.x + threadIdx.x;
    int edge = t >> 2, q = t & 3;
    if (edge >= EE) return;
    int row = ei[edge];
    int col = ei[EE + edge];
    float a  = av[edge];
    float e0 = ef[edge * 3 + 0], e1 = ef[edge * 3 + 1], e2 = ef[edge * 3 + 2];
    const float4* gc = (const float4*)(d_scratch + OFF_GC + col * 32);
    float4 g1v = gc[q];
    float4 c1v = gc[4 + q];
    float* base = d_scratch + OFF_AGG2 + row * 80;
    red_add_v4(base + q * 4, make_float4(a * g1v.x, a * g1v.y, a * g1v.z, a * g1v.w));
    float coeffs[4] = {e0, e1, e2, 1.f};
#pragma unroll
    for (int s = 0; s < 4; s++) {
        float c = coeffs[s];
        red_add_v4(base + 16 + s * 16 + q * 4,
                   make_float4(c * c1v.x, c * c1v.y, c * c1v.z, c * c1v.w));
    }
}

// ---------------- post2: staged contraction + segmented pool; re-zero AGG2 ----------------
__global__ __launch_bounds__(128) void post2_kernel(const int* __restrict__ seg,
                                                    const float* __restrict__ Wg2,
                                                    const float* __restrict__ bg2,
                                                    const float* __restrict__ We2,
                                                    const float* __restrict__ be2,
                                                    const float* __restrict__ root2,
                                                    const float* __restrict__ bias2) {
    extern __shared__ float sA[];                 // [128][97]: agg(80) | c1(16) | pad
    __shared__ __align__(16) float sWg2[512];     // [f<16][o<32]
    __shared__ __align__(16) float sK2[2048];     // [s<4][f<16][o<32] (s=3 -> be2)
    __shared__ __align__(16) float sR2[512];      // [f<16][o<32]
    __shared__ float sBg[32], sB2[32];
    __shared__ int sSeg[128];
    int tid = threadIdx.x;
    int tb = blockIdx.x * 128;
    for (int i = tid; i < 512; i += 128) { sWg2[i] = Wg2[i]; sR2[i] = root2[i]; }
    for (int i = tid; i < 2048; i += 128) sK2[i] = (i < 1536) ? We2[i] : be2[i - 1536];
    if (tid < 32) { sBg[tid] = bg2[tid]; sB2[tid] = bias2[tid]; }
    {
        int n = tb + tid;
        sSeg[tid] = seg[n < NN ? n : (NN - 1)];
    }
    // stage AGG2 tile (coalesced) + immediately re-zero
    for (int i = tid; i < 2560; i += 128) {
        int node = i / 20, k = (i % 20) * 4;
        float4 v = make_float4(0.f, 0.f, 0.f, 0.f);
        if (tb + node < NN) {
            float4* g = (float4*)(d_scratch + OFF_AGG2 + (tb + node) * 80 + k);
            v = *g;
            *g = make_float4(0.f, 0.f, 0.f, 0.f);
        }
        float* s = &sA[node * 97 + k];
        s[0] = v.x; s[1] = v.y; s[2] = v.z; s[3] = v.w;
    }
    // stage c1 (GC second half)
    for (int i = tid; i < 512; i += 128) {
        int node = i >> 2, k = (i & 3) * 4;
        float4 v = make_float4(0.f, 0.f, 0.f, 0.f);
        if (tb + node < NN)
            v = *(const float4*)(d_scratch + OFF_GC + (tb + node) * 32 + 16 + k);
        float* s = &sA[node * 97 + 80 + k];
        s[0] = v.x; s[1] = v.y; s[2] = v.z; s[3] = v.w;
    }
    __syncthreads();
    ull ga[16], ca[16];
#pragma unroll
    for (int k = 0; k < 16; k++) {
        ga[k] = pk2(sBg[2 * k], sBg[2 * k + 1]);
        ca[k] = pk2(sB2[2 * k], sB2[2 * k + 1]);
    }
    float* Ar = &sA[tid * 97];
    // g2: agg cols 0..15 (a*g1)
#pragma unroll
    for (int f = 0; f < 16; f++) {
        ull s = pk2(Ar[f], Ar[f]);
        const ulonglong2* w = (const ulonglong2*)&sWg2[f * 32];
#pragma unroll
        for (int k = 0; k < 8; k++) {
            ulonglong2 wp = w[k];
            fma2(ga[2 * k], s, wp.x);
            fma2(ga[2 * k + 1], s, wp.y);
        }
    }
    // c2 ecc: agg cols 16..79, s-major
#pragma unroll
    for (int si = 0; si < 4; si++) {
#pragma unroll
        for (int f = 0; f < 16; f++) {
            ull s = pk2(Ar[16 + si * 16 + f], Ar[16 + si * 16 + f]);
            const ulonglong2* w = (const ulonglong2*)&sK2[si * 512 + f * 32];
#pragma unroll
            for (int k = 0; k < 8; k++) {
                ulonglong2 wp = w[k];
                fma2(ca[2 * k], s, wp.x);
                fma2(ca[2 * k + 1], s, wp.y);
            }
        }
    }
    // c2 root: c1 at cols 80..95
#pragma unroll
    for (int f = 0; f < 16; f++) {
        ull s = pk2(Ar[80 + f], Ar[80 + f]);
        const ulonglong2* w = (const ulonglong2*)&sR2[f * 32];
#pragma unroll
        for (int k = 0; k < 8; k++) {
            ulonglong2 wp = w[k];
            fma2(ca[2 * k], s, wp.x);
            fma2(ca[2 * k + 1], s, wp.y);
        }
    }
    // relu -> own row sA[tid][0..63] (g2 | c2)
    bool valid = (tb + tid) < NN;
#pragma unroll
    for (int k = 0; k < 16; k++) {
        float2 a = upk(ga[k]);
        Ar[2 * k]     = valid ? fmaxf(a.x, 0.f) : 0.f;
        Ar[2 * k + 1] = valid ? fmaxf(a.y, 0.f) : 0.f;
        float2 b = upk(ca[k]);
        Ar[32 + 2 * k]     = valid ? fmaxf(b.x, 0.f) : 0.f;
        Ar[32 + 2 * k + 1] = valid ? fmaxf(b.y, 0.f) : 0.f;
    }
    __syncthreads();
    // segmented column sum (seg sorted): thread = (col, half)
    int col = tid & 63, half = tid >> 6;
    int r0 = half * 64;
    float acc = 0.f;
    int cur = sSeg[r0];
    for (int r = r0; r < r0 + 64; r++) {
        int sg = sSeg[r];
        if (sg != cur) {
            red_add_f(d_scratch + OFF_POOL + cur * 64 + col, acc);
            acc = 0.f;
            cur = sg;
        }
        acc += sA[r * 97 + col];
    }
    red_add_f(d_scratch + OFF_POOL + cur * 64 + col, acc);
}

// ---------------- head: MLP + sigmoid; re-zero POOL ----------------
__global__ void head_kernel(const float* __restrict__ Wd1, const float* __restrict__ bd1,
                            const float* __restrict__ Wd2, const float* __restrict__ bd2,
                            const float* __restrict__ Wo,  const float* __restrict__ bo,
                            float* __restrict__ out) {
    __shared__ float sW1[64 * 16];
    __shared__ float sb1[16];
    __shared__ float sW2[16 * 8];
    __shared__ float sb2[8];
    __shared__ float sWo[8];
    for (int i = threadIdx.x; i < 1024; i += blockDim.x) sW1[i] = Wd1[i];
    if (threadIdx.x < 16)  sb1[threadIdx.x] = bd1[threadIdx.x];
    if (threadIdx.x < 128) sW2[threadIdx.x] = Wd2[threadIdx.x];
    if (threadIdx.x < 8)   { sb2[threadIdx.x] = bd2[threadIdx.x]; sWo[threadIdx.x] = Wo[threadIdx.x]; }
    __syncthreads();
    int g = blockIdx.x * blockDim.x + threadIdx.x;
    if (g >= GG) return;
    float* pr = d_scratch + OFF_POOL + g * 64;
    float h1[16];
#pragma unroll
    for (int k = 0; k < 16; k++) h1[k] = sb1[k];
    for (int f = 0; f < 64; f++) {
        float v = pr[f];
#pragma unroll
        for (int k = 0; k < 16; k++) h1[k] += v * sW1[f * 16 + k];
    }
#pragma unroll
    for (int k = 0; k < 16; k++) h1[k] = fmaxf(h1[k], 0.f);
    float h2[8];
#pragma unroll
    for (int m = 0; m < 8; m++) h2[m] = sb2[m];
#pragma unroll
    for (int k = 0; k < 16; k++) {
        float v = h1[k];
#pragma unroll
        for (int m = 0; m < 8; m++) h2[m] += v * sW2[k * 8 + m];
    }
    float z = bo[0];
#pragma unroll
    for (int m = 0; m < 8; m++) z += fmaxf(h2[m], 0.f) * sWo[m];
    out[g] = 1.f / (1.f + expf(-z));
    // self-restoring zero for next replay
    float4* pz = (float4*)pr;
#pragma unroll
    for (int k = 0; k < 16; k++) pz[k] = make_float4(0.f, 0.f, 0.f, 0.f);
}

// ---------------- launch ----------------
extern "C" void kernel_launch(void* const* d_in, const int* in_sizes, int n_in,
                              void* d_out, int out_size) {
    const float* x     = (const float*)d_in[0];
    const float* av    = (const float*)d_in[1];
    const float* ef    = (const float*)d_in[2];
    const int*   ei    = (const int*)  d_in[3];
    const int*   seg   = (const int*)  d_in[4];
    const float* Wg1   = (const float*)d_in[5];
    const float* bg1   = (const float*)d_in[6];
    const float* Wg2   = (const float*)d_in[7];
    const float* bg2   = (const float*)d_in[8];
    const float* We1   = (const float*)d_in[9];
    const float* be1   = (const float*)d_in[10];
    const float* root1 = (const float*)d_in[11];
    const float* bias1 = (const float*)d_in[12];
    const float* We2   = (const float*)d_in[13];
    const float* be2   = (const float*)d_in[14];
    const float* root2 = (const float*)d_in[15];
    const float* bias2 = (const float*)d_in[16];
    const float* Wd1   = (const float*)d_in[17];
    const float* bd1   = (const float*)d_in[18];
    const float* Wd2   = (const float*)d_in[19];
    const float* bd2   = (const float*)d_in[20];
    const float* Wo    = (const float*)d_in[21];
    const float* bo    = (const float*)d_in[22];
    float* out = (float*)d_out;

    constexpr int NTILES = (NN + 127) / 128;
    constexpr int SMEM1 = 128 * 77 * 4;   // 39424 B
    constexpr int SMEM2 = 128 * 97 * 4;   // 49664 B (> 48K -> needs attr)
    cudaFuncSetAttribute(post2_kernel, cudaFuncAttributeMaxDynamicSharedMemorySize, SMEM2);

    init_kernel<<<(NN * 3 + 255) / 256, 256>>>(x);
    pass1_kernel<<<(EE * 5 + 319) / 320, 320>>>(ei, av, ef);
    post1_kernel<<<NTILES, 128, SMEM1>>>(Wg1, bg1, We1, be1, root1, bias1);
    pass2_kernel<<<(EE * 4 + 255) / 256, 256>>>(ei, av, ef);
    post2_kernel<<<NTILES, 128, SMEM2>>>(seg, Wg2, bg2, We2, be2, root2, bias2);
    head_kernel<<<2, 256>>>(Wd1, bd1, Wd2, bd2, Wo, bo, out);
}

// round 10
// speedup vs baseline: 1.7472x; 1.7472x over previous
#include <cuda_runtime.h>

#define NN 60000
#define EE 240000
#define GG 512

// ---------------- scratch layout (floats) ----------------
// X12  : N*12  (x padded to 12 features)
// G1   : N*16  (gcn layer-1 output)
// C1   : N*16  (ecc layer-1 output)
// -- zeroed region --
// AGG1 : N*64  ([a*x | e0*x | e1*x | e2*x | 1*x] each 12-wide, +4 pad)
// AGG2 : N*80  ([a*g1 16 | e0*c1 | e1*c1 | e2*c1 | 1*c1 each 16])
// POOL : G*64  ([g2 pooled 32 | c2 pooled 32])
constexpr int OFF_X12  = 0;
constexpr int OFF_G1   = OFF_X12 + NN * 12;
constexpr int OFF_C1   = OFF_G1  + NN * 16;
constexpr int OFF_ZERO = OFF_C1  + NN * 16;
constexpr int OFF_AGG1 = OFF_ZERO;
constexpr int OFF_AGG2 = OFF_AGG1 + NN * 64;
constexpr int OFF_POOL = OFF_AGG2 + NN * 80;
constexpr int SCRATCH_TOTAL = OFF_POOL + GG * 64;
constexpr int ZERO_COUNT = SCRATCH_TOTAL - OFF_ZERO;

__device__ __align__(16) float d_scratch[SCRATCH_TOTAL];

// ---------------- helpers ----------------
__device__ __forceinline__ void red_add_v4(float* addr, float4 v) {
    asm volatile("red.global.add.v4.f32 [%0], {%1, %2, %3, %4};"
                 :: "l"(addr), "f"(v.x), "f"(v.y), "f"(v.z), "f"(v.w)
                 : "memory");
}

typedef unsigned long long ull;

__device__ __forceinline__ ull pk2(float lo, float hi) {
    ull r;
    asm("mov.b64 %0, {%1, %2};" : "=l"(r) : "f"(lo), "f"(hi));
    return r;
}
__device__ __forceinline__ void fma2(ull& acc, ull a, ull b) {
    asm("fma.rn.f32x2 %0, %1, %2, %0;" : "+l"(acc) : "l"(a), "l"(b));
}
__device__ __forceinline__ float2 upk(ull v) {
    float2 o;
    asm("mov.b64 {%0, %1}, %2;" : "=f"(o.x), "=f"(o.y) : "l"(v));
    return o;
}

// ---------------- kernels ----------------
// zero accumulators + build padded X12
__global__ void init_kernel(const float* __restrict__ x) {
    int i = blockIdx.x * blockDim.x + threadIdx.x;
    constexpr int ZC4 = ZERO_COUNT / 4;
    if (i < ZC4) {
        ((float4*)(d_scratch + OFF_ZERO))[i] = make_float4(0.f, 0.f, 0.f, 0.f);
        return;
    }
    int j = i - ZC4;
    if (j < NN * 3) {
        int node = j / 3, p = j - node * 3;
        int f0 = p * 4;
        const float* xr = x + node * 10;
        float4 v;
        v.x = (f0 + 0 < 10) ? xr[f0 + 0] : 0.f;
        v.y = (f0 + 1 < 10) ? xr[f0 + 1] : 0.f;
        v.z = (f0 + 2 < 10) ? xr[f0 + 2] : 0.f;
        v.w = (f0 + 3 < 10) ? xr[f0 + 3] : 0.f;
        ((float4*)(d_scratch + OFF_X12))[node * 3 + p] = v;
    }
}

// pass1: 5 threads/edge, each applies one coefficient (a, e0, e1, e2, 1) to x12[col]
__global__ void pass1_kernel(const int* __restrict__ ei,
                             const float* __restrict__ av,
                             const float* __restrict__ ef) {
    int t = blockIdx.x * blockDim.x + threadIdx.x;
    int edge = t / 5;
    int q = t - edge * 5;
    if (edge >= EE) return;
    int row = ei[edge];
    int col = ei[EE + edge];
    float coeff;
    if (q == 0)      coeff = av[edge];
    else if (q < 4)  coeff = ef[edge * 3 + (q - 1)];
    else             coeff = 1.f;
    const float4* xp = (const float4*)(d_scratch + OFF_X12 + col * 12);
    float* dst = d_scratch + OFF_AGG1 + row * 64 + q * 12;
#pragma unroll
    for (int k = 0; k < 3; k++) {
        float4 v = xp[k];
        red_add_v4(dst + k * 4,
                   make_float4(coeff * v.x, coeff * v.y, coeff * v.z, coeff * v.w));
    }
}

// post1: per-node contractions -> g1[16], c1[16]
__global__ void post1_kernel(const float* __restrict__ Wg1, const float* __restrict__ bg1,
                             const float* __restrict__ We1, const float* __restrict__ be1,
                             const float* __restrict__ root1, const float* __restrict__ bias1) {
    __shared__ __align__(16) float sWg1[160];
    __shared__ __align__(16) float sK1[640];   // [s=0..3][f<10][o<16]; s<3: We1, s=3: be1
    __shared__ __align__(16) float sR1[160];
    __shared__ float sBg[16], sB1[16];
    int tid = threadIdx.x;
    for (int i = tid; i < 160; i += blockDim.x) { sWg1[i] = Wg1[i]; sR1[i] = root1[i]; }
    for (int i = tid; i < 640; i += blockDim.x) sK1[i] = (i < 480) ? We1[i] : be1[i - 480];
    if (tid < 16) { sBg[tid] = bg1[tid]; sB1[tid] = bias1[tid]; }
    __syncthreads();
    int node = blockIdx.x * blockDim.x + tid;
    if (node >= NN) return;

    ull ga[8], ca[8];
#pragma unroll
    for (int k = 0; k < 8; k++) {
        ga[k] = pk2(sBg[2 * k], sBg[2 * k + 1]);
        ca[k] = pk2(sB1[2 * k], sB1[2 * k + 1]);
    }
    const float4* ap = (const float4*)(d_scratch + OFF_AGG1 + node * 64);

    // gcn part: channels 0..9 (a-weighted x), chunks 0..2
#pragma unroll
    for (int c4 = 0; c4 < 3; c4++) {
        float4 v = ap[c4];
        float vv[4] = {v.x, v.y, v.z, v.w};
#pragma unroll
        for (int j = 0; j < 4; j++) {
            int f = c4 * 4 + j;
            if (f < 10) {
                ull s = pk2(vv[j], vv[j]);
                const ulonglong2* w = (const ulonglong2*)&sWg1[f * 16];
#pragma unroll
                for (int k = 0; k < 4; k++) {
                    ulonglong2 wp = w[k];
                    fma2(ga[2 * k], s, wp.x);
                    fma2(ga[2 * k + 1], s, wp.y);
                }
            }
        }
    }
    // ecc aggregated part: channels 12..59 -> (s_i, f), chunks 3..14
#pragma unroll
    for (int c4 = 3; c4 < 15; c4++) {
        float4 v = ap[c4];
        float vv[4] = {v.x, v.y, v.z, v.w};
#pragma unroll
        for (int j = 0; j < 4; j++) {
            int fi = c4 * 4 + j - 12;
            int s_i = fi / 12, f = fi - s_i * 12;
            if (f < 10) {
                ull s = pk2(vv[j], vv[j]);
                const ulonglong2* w = (const ulonglong2*)&sK1[s_i * 160 + f * 16];
#pragma unroll
                for (int k = 0; k < 4; k++) {
                    ulonglong2 wp = w[k];
                    fma2(ca[2 * k], s, wp.x);
                    fma2(ca[2 * k + 1], s, wp.y);
                }
            }
        }
    }
    // root term: x12 itself
    const float4* xp = (const float4*)(d_scratch + OFF_X12 + node * 12);
#pragma unroll
    for (int c4 = 0; c4 < 3; c4++) {
        float4 v = xp[c4];
        float vv[4] = {v.x, v.y, v.z, v.w};
#pragma unroll
        for (int j = 0; j < 4; j++) {
            int f = c4 * 4 + j;
            if (f < 10) {
                ull s = pk2(vv[j], vv[j]);
                const ulonglong2* w = (const ulonglong2*)&sR1[f * 16];
#pragma unroll
                for (int k = 0; k < 4; k++) {
                    ulonglong2 wp = w[k];
                    fma2(ca[2 * k], s, wp.x);
                    fma2(ca[2 * k + 1], s, wp.y);
                }
            }
        }
    }
    // relu + store
    float4* g1o = (float4*)(d_scratch + OFF_G1 + node * 16);
    float4* c1o = (float4*)(d_scratch + OFF_C1 + node * 16);
#pragma unroll
    for (int k = 0; k < 4; k++) {
        float2 a0 = upk(ga[2 * k]), a1 = upk(ga[2 * k + 1]);
        g1o[k] = make_float4(fmaxf(a0.x, 0.f), fmaxf(a0.y, 0.f),
                             fmaxf(a1.x, 0.f), fmaxf(a1.y, 0.f));
        float2 b0 = upk(ca[2 * k]), b1 = upk(ca[2 * k + 1]);
        c1o[k] = make_float4(fmaxf(b0.x, 0.f), fmaxf(b0.y, 0.f),
                             fmaxf(b1.x, 0.f), fmaxf(b1.y, 0.f));
    }
}

// pass2: 4 threads/edge, each handles a 4-feature slice of g1/c1
__global__ void pass2_kernel(const int* __restrict__ ei,
                             const float* __restrict__ av,
                             const float* __restrict__ ef) {
    int t = blockIdx.x * blockDim.x + threadIdx.x;
    int edge = t >> 2, q = t & 3;
    if (edge >= EE) return;
    int row = ei[edge];
    int col = ei[EE + edge];
    float a  = av[edge];
    float e0 = ef[edge * 3 + 0], e1 = ef[edge * 3 + 1], e2 = ef[edge * 3 + 2];
    float4 g1v = ((const float4*)(d_scratch + OFF_G1 + col * 16))[q];
    float4 c1v = ((const float4*)(d_scratch + OFF_C1 + col * 16))[q];
    float* base = d_scratch + OFF_AGG2 + row * 80;
    red_add_v4(base + q * 4, make_float4(a * g1v.x, a * g1v.y, a * g1v.z, a * g1v.w));
    float coeffs[4] = {e0, e1, e2, 1.f};
#pragma unroll
    for (int s = 0; s < 4; s++) {
        float c = coeffs[s];
        red_add_v4(base + 16 + s * 16 + q * 4,
                   make_float4(c * c1v.x, c * c1v.y, c * c1v.z, c * c1v.w));
    }
}

// post2: per-node contractions -> g2[32], c2[32], relu, per-graph pool via REDs
__global__ void post2_kernel(const int* __restrict__ seg,
                             const float* __restrict__ Wg2, const float* __restrict__ bg2,
                             const float* __restrict__ We2, const float* __restrict__ be2,
                             const float* __restrict__ root2, const float* __restrict__ bias2) {
    __shared__ __align__(16) float sWg2[512];
    __shared__ __align__(16) float sK2[2048];  // [s][f<16][o<32]; s<3: We2, s=3: be2
    __shared__ __align__(16) float sR2[512];
    __shared__ float sBg[32], sB2[32];
    int tid = threadIdx.x;
    for (int i = tid; i < 512; i += blockDim.x) { sWg2[i] = Wg2[i]; sR2[i] = root2[i]; }
    for (int i = tid; i < 2048; i += blockDim.x) sK2[i] = (i < 1536) ? We2[i] : be2[i - 1536];
    if (tid < 32) { sBg[tid] = bg2[tid]; sB2[tid] = bias2[tid]; }
    __syncthreads();
    int node = blockIdx.x * blockDim.x + tid;
    if (node >= NN) return;

    ull ga[16], ca[16];
#pragma unroll
    for (int k = 0; k < 16; k++) {
        ga[k] = pk2(sBg[2 * k], sBg[2 * k + 1]);
        ca[k] = pk2(sB2[2 * k], sB2[2 * k + 1]);
    }
    const float4* ap = (const float4*)(d_scratch + OFF_AGG2 + node * 80);

    // g2: inputs agg[0..15]
#pragma unroll
    for (int c4 = 0; c4 < 4; c4++) {
        float4 v = ap[c4];
        float vv[4] = {v.x, v.y, v.z, v.w};
#pragma unroll
        for (int j = 0; j < 4; j++) {
            int f = c4 * 4 + j;
            ull s = pk2(vv[j], vv[j]);
            const ulonglong2* w = (const ulonglong2*)&sWg2[f * 32];
#pragma unroll
            for (int k = 0; k < 8; k++) {
                ulonglong2 wp = w[k];
                fma2(ga[2 * k], s, wp.x);
                fma2(ga[2 * k + 1], s, wp.y);
            }
        }
    }
    // c2: inputs agg[16..79] -> (s_i, f)
#pragma unroll
    for (int c4 = 4; c4 < 20; c4++) {
        float4 v = ap[c4];
        float vv[4] = {v.x, v.y, v.z, v.w};
#pragma unroll
        for (int j = 0; j < 4; j++) {
            int fi = (c4 - 4) * 4 + j;
            int s_i = fi >> 4, f = fi & 15;
            ull s = pk2(vv[j], vv[j]);
            const ulonglong2* w = (const ulonglong2*)&sK2[s_i * 512 + f * 32];
#pragma unroll
            for (int k = 0; k < 8; k++) {
                ulonglong2 wp = w[k];
                fma2(ca[2 * k], s, wp.x);
                fma2(ca[2 * k + 1], s, wp.y);
            }
        }
    }
    // root term: c1
    const float4* cp = (const float4*)(d_scratch + OFF_C1 + node * 16);
#pragma unroll
    for (int c4 = 0; c4 < 4; c4++) {
        float4 v = cp[c4];
        float vv[4] = {v.x, v.y, v.z, v.w};
#pragma unroll
        for (int j = 0; j < 4; j++) {
            int f = c4 * 4 + j;
            ull s = pk2(vv[j], vv[j]);
            const ulonglong2* w = (const ulonglong2*)&sR2[f * 32];
#pragma unroll
            for (int k = 0; k < 8; k++) {
                ulonglong2 wp = w[k];
                fma2(ca[2 * k], s, wp.x);
                fma2(ca[2 * k + 1], s, wp.y);
            }
        }
    }
    // relu + pool into POOL[g][0..31]=g2, [32..63]=c2
    int g = seg[node];
    float* pb = d_scratch + OFF_POOL + g * 64;
#pragma unroll
    for (int k = 0; k < 8; k++) {
        float2 a0 = upk(ga[2 * k]), a1 = upk(ga[2 * k + 1]);
        red_add_v4(pb + k * 4,
                   make_float4(fmaxf(a0.x, 0.f), fmaxf(a0.y, 0.f),
                               fmaxf(a1.x, 0.f), fmaxf(a1.y, 0.f)));
        float2 b0 = upk(ca[2 * k]), b1 = upk(ca[2 * k + 1]);
        red_add_v4(pb + 32 + k * 4,
                   make_float4(fmaxf(b0.x, 0.f), fmaxf(b0.y, 0.f),
                               fmaxf(b1.x, 0.f), fmaxf(b1.y, 0.f)));
    }
}

// MLP head: [G,64] -> 16 -> 8 -> sigmoid -> out[G]
__global__ void head_kernel(const float* __restrict__ Wd1, const float* __restrict__ bd1,
                            const float* __restrict__ Wd2, const float* __restrict__ bd2,
                            const float* __restrict__ Wo,  const float* __restrict__ bo,
                            float* __restrict__ out) {
    __shared__ float sW1[64 * 16];
    __shared__ float sb1[16];
    __shared__ float sW2[16 * 8];
    __shared__ float sb2[8];
    __shared__ float sWo[8];
    for (int i = threadIdx.x; i < 1024; i += blockDim.x) sW1[i] = Wd1[i];
    if (threadIdx.x < 16)  sb1[threadIdx.x] = bd1[threadIdx.x];
    if (threadIdx.x < 128) sW2[threadIdx.x] = Wd2[threadIdx.x];
    if (threadIdx.x < 8)   { sb2[threadIdx.x] = bd2[threadIdx.x]; sWo[threadIdx.x] = Wo[threadIdx.x]; }
    __syncthreads();
    int g = blockIdx.x * blockDim.x + threadIdx.x;
    if (g >= GG) return;
    const float* pr = d_scratch + OFF_POOL + g * 64;
    float h1[16];
#pragma unroll
    for (int k = 0; k < 16; k++) h1[k] = sb1[k];
    for (int f = 0; f < 64; f++) {
        float v = pr[f];
#pragma unroll
        for (int k = 0; k < 16; k++) h1[k] += v * sW1[f * 16 + k];
    }
#pragma unroll
    for (int k = 0; k < 16; k++) h1[k] = fmaxf(h1[k], 0.f);
    float h2[8];
#pragma unroll
    for (int m = 0; m < 8; m++) h2[m] = sb2[m];
#pragma unroll
    for (int k = 0; k < 16; k++) {
        float v = h1[k];
#pragma unroll
        for (int m = 0; m < 8; m++) h2[m] += v * sW2[k * 8 + m];
    }
    float z = bo[0];
#pragma unroll
    for (int m = 0; m < 8; m++) z += fmaxf(h2[m], 0.f) * sWo[m];
    out[g] = 1.f / (1.f + expf(-z));
}

// ---------------- launch ----------------
extern "C" void kernel_launch(void* const* d_in, const int* in_sizes, int n_in,
                              void* d_out, int out_size) {
    const float* x     = (const float*)d_in[0];
    const float* av    = (const float*)d_in[1];
    const float* ef    = (const float*)d_in[2];
    const int*   ei    = (const int*)  d_in[3];
    const int*   seg   = (const int*)  d_in[4];
    const float* Wg1   = (const float*)d_in[5];
    const float* bg1   = (const float*)d_in[6];
    const float* Wg2   = (const float*)d_in[7];
    const float* bg2   = (const float*)d_in[8];
    const float* We1   = (const float*)d_in[9];
    const float* be1   = (const float*)d_in[10];
    const float* root1 = (const float*)d_in[11];
    const float* bias1 = (const float*)d_in[12];
    const float* We2   = (const float*)d_in[13];
    const float* be2   = (const float*)d_in[14];
    const float* root2 = (const float*)d_in[15];
    const float* bias2 = (const float*)d_in[16];
    const float* Wd1   = (const float*)d_in[17];
    const float* bd1   = (const float*)d_in[18];
    const float* Wd2   = (const float*)d_in[19];
    const float* bd2   = (const float*)d_in[20];
    const float* Wo    = (const float*)d_in[21];
    const float* bo    = (const float*)d_in[22];
    float* out = (float*)d_out;

    constexpr int INIT_ITEMS = ZERO_COUNT / 4 + NN * 3;
    init_kernel<<<(INIT_ITEMS + 255) / 256, 256>>>(x);
    pass1_kernel<<<(EE * 5 + 319) / 320, 320>>>(ei, av, ef);
    post1_kernel<<<(NN + 127) / 128, 128>>>(Wg1, bg1, We1, be1, root1, bias1);
    pass2_kernel<<<(EE * 4 + 255) / 256, 256>>>(ei, av, ef);
    post2_kernel<<<(NN + 127) / 128, 128>>>(seg, Wg2, bg2, We2, be2, root2, bias2);
    head_kernel<<<2, 256>>>(Wd1, bd1, Wd2, bd2, Wo, bo, out);
}

// round 11
// speedup vs baseline: 1.7922x; 1.0258x over previous
#include <cuda_runtime.h>

#define NN 60000
#define EE 240000
#define GG 512

// ---------------- scratch layout (floats) ----------------
// X12  : N*12  (x padded to 12 features)
// G1   : N*16  (gcn layer-1 output)
// C1   : N*16  (ecc layer-1 output)
// -- zeroed region --
// AGG1 : N*64  ([a*x | e0*x | e1*x | e2*x | 1*x] each 12-wide, +4 pad)
// AGG2 : N*80  ([a*g1 16 | e0*c1 | e1*c1 | e2*c1 | 1*c1 each 16])
// POOL : G*64  ([g2 pooled 32 | c2 pooled 32])
constexpr int OFF_X12  = 0;
constexpr int OFF_G1   = OFF_X12 + NN * 12;
constexpr int OFF_C1   = OFF_G1  + NN * 16;
constexpr int OFF_ZERO = OFF_C1  + NN * 16;
constexpr int OFF_AGG1 = OFF_ZERO;
constexpr int OFF_AGG2 = OFF_AGG1 + NN * 64;
constexpr int OFF_POOL = OFF_AGG2 + NN * 80;
constexpr int SCRATCH_TOTAL = OFF_POOL + GG * 64;
constexpr int ZERO_COUNT = SCRATCH_TOTAL - OFF_ZERO;

__device__ __align__(16) float d_scratch[SCRATCH_TOTAL];

// ---------------- helpers ----------------
__device__ __forceinline__ void red_add_v4(float* addr, float4 v) {
    asm volatile("red.global.add.v4.f32 [%0], {%1, %2, %3, %4};"
                 :: "l"(addr), "f"(v.x), "f"(v.y), "f"(v.z), "f"(v.w)
                 : "memory");
}

typedef unsigned long long ull;

__device__ __forceinline__ ull pk2(float lo, float hi) {
    ull r;
    asm("mov.b64 %0, {%1, %2};" : "=l"(r) : "f"(lo), "f"(hi));
    return r;
}
__device__ __forceinline__ void fma2(ull& acc, ull a, ull b) {
    asm("fma.rn.f32x2 %0, %1, %2, %0;" : "+l"(acc) : "l"(a), "l"(b));
}
__device__ __forceinline__ float2 upk(ull v) {
    float2 o;
    asm("mov.b64 {%0, %1}, %2;" : "=f"(o.x), "=f"(o.y) : "l"(v));
    return o;
}

// ---------------- kernels ----------------
// zero accumulators + build padded X12
__global__ void init_kernel(const float* __restrict__ x) {
    int i = blockIdx.x * blockDim.x + threadIdx.x;
    constexpr int ZC4 = ZERO_COUNT / 4;
    if (i < ZC4) {
        ((float4*)(d_scratch + OFF_ZERO))[i] = make_float4(0.f, 0.f, 0.f, 0.f);
        return;
    }
    int j = i - ZC4;
    if (j < NN * 3) {
        int node = j / 3, p = j - node * 3;
        int f0 = p * 4;
        const float* xr = x + node * 10;
        float4 v;
        v.x = (f0 + 0 < 10) ? xr[f0 + 0] : 0.f;
        v.y = (f0 + 1 < 10) ? xr[f0 + 1] : 0.f;
        v.z = (f0 + 2 < 10) ? xr[f0 + 2] : 0.f;
        v.w = (f0 + 3 < 10) ? xr[f0 + 3] : 0.f;
        ((float4*)(d_scratch + OFF_X12))[node * 3 + p] = v;
    }
}

// pass1: 3 threads/edge; each thread owns one 4-feature chunk of x12[col]
// and scatters it under all 5 coefficients (a, e0, e1, e2, 1).
__global__ void pass1_kernel(const int* __restrict__ ei,
                             const float* __restrict__ av,
                             const float* __restrict__ ef) {
    int t = blockIdx.x * blockDim.x + threadIdx.x;
    int edge = t / 3;
    int chunk = t - edge * 3;
    if (edge >= EE) return;
    int row = ei[edge];
    int col = ei[EE + edge];
    float a  = av[edge];
    float e0 = ef[edge * 3 + 0], e1 = ef[edge * 3 + 1], e2 = ef[edge * 3 + 2];
    float4 v = ((const float4*)(d_scratch + OFF_X12 + col * 12))[chunk];
    float* dst = d_scratch + OFF_AGG1 + row * 64 + chunk * 4;
    red_add_v4(dst,      make_float4(a * v.x,  a * v.y,  a * v.z,  a * v.w));
    red_add_v4(dst + 12, make_float4(e0 * v.x, e0 * v.y, e0 * v.z, e0 * v.w));
    red_add_v4(dst + 24, make_float4(e1 * v.x, e1 * v.y, e1 * v.z, e1 * v.w));
    red_add_v4(dst + 36, make_float4(e2 * v.x, e2 * v.y, e2 * v.z, e2 * v.w));
    red_add_v4(dst + 48, v);
}

// post1: per-node contractions -> g1[16], c1[16]
__global__ void post1_kernel(const float* __restrict__ Wg1, const float* __restrict__ bg1,
                             const float* __restrict__ We1, const float* __restrict__ be1,
                             const float* __restrict__ root1, const float* __restrict__ bias1) {
    __shared__ __align__(16) float sWg1[160];
    __shared__ __align__(16) float sK1[640];   // [s=0..3][f<10][o<16]; s<3: We1, s=3: be1
    __shared__ __align__(16) float sR1[160];
    __shared__ float sBg[16], sB1[16];
    int tid = threadIdx.x;
    for (int i = tid; i < 160; i += blockDim.x) { sWg1[i] = Wg1[i]; sR1[i] = root1[i]; }
    for (int i = tid; i < 640; i += blockDim.x) sK1[i] = (i < 480) ? We1[i] : be1[i - 480];
    if (tid < 16) { sBg[tid] = bg1[tid]; sB1[tid] = bias1[tid]; }
    __syncthreads();
    int node = blockIdx.x * blockDim.x + tid;
    if (node >= NN) return;

    ull ga[8], ca[8];
#pragma unroll
    for (int k = 0; k < 8; k++) {
        ga[k] = pk2(sBg[2 * k], sBg[2 * k + 1]);
        ca[k] = pk2(sB1[2 * k], sB1[2 * k + 1]);
    }
    const float4* ap = (const float4*)(d_scratch + OFF_AGG1 + node * 64);

    // gcn part: channels 0..9 (a-weighted x), chunks 0..2
#pragma unroll
    for (int c4 = 0; c4 < 3; c4++) {
        float4 v = ap[c4];
        float vv[4] = {v.x, v.y, v.z, v.w};
#pragma unroll
        for (int j = 0; j < 4; j++) {
            int f = c4 * 4 + j;
            if (f < 10) {
                ull s = pk2(vv[j], vv[j]);
                const ulonglong2* w = (const ulonglong2*)&sWg1[f * 16];
#pragma unroll
                for (int k = 0; k < 4; k++) {
                    ulonglong2 wp = w[k];
                    fma2(ga[2 * k], s, wp.x);
                    fma2(ga[2 * k + 1], s, wp.y);
                }
            }
        }
    }
    // ecc aggregated part: channels 12..59 -> (s_i, f), chunks 3..14
#pragma unroll
    for (int c4 = 3; c4 < 15; c4++) {
        float4 v = ap[c4];
        float vv[4] = {v.x, v.y, v.z, v.w};
#pragma unroll
        for (int j = 0; j < 4; j++) {
            int fi = c4 * 4 + j - 12;
            int s_i = fi / 12, f = fi - s_i * 12;
            if (f < 10) {
                ull s = pk2(vv[j], vv[j]);
                const ulonglong2* w = (const ulonglong2*)&sK1[s_i * 160 + f * 16];
#pragma unroll
                for (int k = 0; k < 4; k++) {
                    ulonglong2 wp = w[k];
                    fma2(ca[2 * k], s, wp.x);
                    fma2(ca[2 * k + 1], s, wp.y);
                }
            }
        }
    }
    // root term: x12 itself
    const float4* xp = (const float4*)(d_scratch + OFF_X12 + node * 12);
#pragma unroll
    for (int c4 = 0; c4 < 3; c4++) {
        float4 v = xp[c4];
        float vv[4] = {v.x, v.y, v.z, v.w};
#pragma unroll
        for (int j = 0; j < 4; j++) {
            int f = c4 * 4 + j;
            if (f < 10) {
                ull s = pk2(vv[j], vv[j]);
                const ulonglong2* w = (const ulonglong2*)&sR1[f * 16];
#pragma unroll
                for (int k = 0; k < 4; k++) {
                    ulonglong2 wp = w[k];
                    fma2(ca[2 * k], s, wp.x);
                    fma2(ca[2 * k + 1], s, wp.y);
                }
            }
        }
    }
    // relu + store
    float4* g1o = (float4*)(d_scratch + OFF_G1 + node * 16);
    float4* c1o = (float4*)(d_scratch + OFF_C1 + node * 16);
#pragma unroll
    for (int k = 0; k < 4; k++) {
        float2 a0 = upk(ga[2 * k]), a1 = upk(ga[2 * k + 1]);
        g1o[k] = make_float4(fmaxf(a0.x, 0.f), fmaxf(a0.y, 0.f),
                             fmaxf(a1.x, 0.f), fmaxf(a1.y, 0.f));
        float2 b0 = upk(ca[2 * k]), b1 = upk(ca[2 * k + 1]);
        c1o[k] = make_float4(fmaxf(b0.x, 0.f), fmaxf(b0.y, 0.f),
                             fmaxf(b1.x, 0.f), fmaxf(b1.y, 0.f));
    }
}

// pass2: 4 threads/edge, each handles a 4-feature slice of g1/c1
__global__ void pass2_kernel(const int* __restrict__ ei,
                             const float* __restrict__ av,
                             const float* __restrict__ ef) {
    int t = blockIdx.x * blockDim.x + threadIdx.x;
    int edge = t >> 2, q = t & 3;
    if (edge >= EE) return;
    int row = ei[edge];
    int col = ei[EE + edge];
    float a  = av[edge];
    float e0 = ef[edge * 3 + 0], e1 = ef[edge * 3 + 1], e2 = ef[edge * 3 + 2];
    float4 g1v = ((const float4*)(d_scratch + OFF_G1 + col * 16))[q];
    float4 c1v = ((const float4*)(d_scratch + OFF_C1 + col * 16))[q];
    float* base = d_scratch + OFF_AGG2 + row * 80;
    red_add_v4(base + q * 4, make_float4(a * g1v.x, a * g1v.y, a * g1v.z, a * g1v.w));
    float coeffs[4] = {e0, e1, e2, 1.f};
#pragma unroll
    for (int s = 0; s < 4; s++) {
        float c = coeffs[s];
        red_add_v4(base + 16 + s * 16 + q * 4,
                   make_float4(c * c1v.x, c * c1v.y, c * c1v.z, c * c1v.w));
    }
}

// post2: per-node contractions -> g2[32], c2[32], relu, per-graph pool via REDs
__global__ void post2_kernel(const int* __restrict__ seg,
                             const float* __restrict__ Wg2, const float* __restrict__ bg2,
                             const float* __restrict__ We2, const float* __restrict__ be2,
                             const float* __restrict__ root2, const float* __restrict__ bias2) {
    __shared__ __align__(16) float sWg2[512];
    __shared__ __align__(16) float sK2[2048];  // [s][f<16][o<32]; s<3: We2, s=3: be2
    __shared__ __align__(16) float sR2[512];
    __shared__ float sBg[32], sB2[32];
    int tid = threadIdx.x;
    for (int i = tid; i < 512; i += blockDim.x) { sWg2[i] = Wg2[i]; sR2[i] = root2[i]; }
    for (int i = tid; i < 2048; i += blockDim.x) sK2[i] = (i < 1536) ? We2[i] : be2[i - 1536];
    if (tid < 32) { sBg[tid] = bg2[tid]; sB2[tid] = bias2[tid]; }
    __syncthreads();
    int node = blockIdx.x * blockDim.x + tid;
    if (node >= NN) return;

    ull ga[16], ca[16];
#pragma unroll
    for (int k = 0; k < 16; k++) {
        ga[k] = pk2(sBg[2 * k], sBg[2 * k + 1]);
        ca[k] = pk2(sB2[2 * k], sB2[2 * k + 1]);
    }
    const float4* ap = (const float4*)(d_scratch + OFF_AGG2 + node * 80);

    // g2: inputs agg[0..15]
#pragma unroll
    for (int c4 = 0; c4 < 4; c4++) {
        float4 v = ap[c4];
        float vv[4] = {v.x, v.y, v.z, v.w};
#pragma unroll
        for (int j = 0; j < 4; j++) {
            int f = c4 * 4 + j;
            ull s = pk2(vv[j], vv[j]);
            const ulonglong2* w = (const ulonglong2*)&sWg2[f * 32];
#pragma unroll
            for (int k = 0; k < 8; k++) {
                ulonglong2 wp = w[k];
                fma2(ga[2 * k], s, wp.x);
                fma2(ga[2 * k + 1], s, wp.y);
            }
        }
    }
    // c2: inputs agg[16..79] -> (s_i, f)
#pragma unroll
    for (int c4 = 4; c4 < 20; c4++) {
        float4 v = ap[c4];
        float vv[4] = {v.x, v.y, v.z, v.w};
#pragma unroll
        for (int j = 0; j < 4; j++) {
            int fi = (c4 - 4) * 4 + j;
            int s_i = fi >> 4, f = fi & 15;
            ull s = pk2(vv[j], vv[j]);
            const ulonglong2* w = (const ulonglong2*)&sK2[s_i * 512 + f * 32];
#pragma unroll
            for (int k = 0; k < 8; k++) {
                ulonglong2 wp = w[k];
                fma2(ca[2 * k], s, wp.x);
                fma2(ca[2 * k + 1], s, wp.y);
            }
        }
    }
    // root term: c1
    const float4* cp = (const float4*)(d_scratch + OFF_C1 + node * 16);
#pragma unroll
    for (int c4 = 0; c4 < 4; c4++) {
        float4 v = cp[c4];
        float vv[4] = {v.x, v.y, v.z, v.w};
#pragma unroll
        for (int j = 0; j < 4; j++) {
            int f = c4 * 4 + j;
            ull s = pk2(vv[j], vv[j]);
            const ulonglong2* w = (const ulonglong2*)&sR2[f * 32];
#pragma unroll
            for (int k = 0; k < 8; k++) {
                ulonglong2 wp = w[k];
                fma2(ca[2 * k], s, wp.x);
                fma2(ca[2 * k + 1], s, wp.y);
            }
        }
    }
    // relu + pool into POOL[g][0..31]=g2, [32..63]=c2
    int g = seg[node];
    float* pb = d_scratch + OFF_POOL + g * 64;
#pragma unroll
    for (int k = 0; k < 8; k++) {
        float2 a0 = upk(ga[2 * k]), a1 = upk(ga[2 * k + 1]);
        red_add_v4(pb + k * 4,
                   make_float4(fmaxf(a0.x, 0.f), fmaxf(a0.y, 0.f),
                               fmaxf(a1.x, 0.f), fmaxf(a1.y, 0.f)));
        float2 b0 = upk(ca[2 * k]), b1 = upk(ca[2 * k + 1]);
        red_add_v4(pb + 32 + k * 4,
                   make_float4(fmaxf(b0.x, 0.f), fmaxf(b0.y, 0.f),
                               fmaxf(b1.x, 0.f), fmaxf(b1.y, 0.f)));
    }
}

// MLP head: [G,64] -> 16 -> 8 -> sigmoid -> out[G]
__global__ void head_kernel(const float* __restrict__ Wd1, const float* __restrict__ bd1,
                            const float* __restrict__ Wd2, const float* __restrict__ bd2,
                            const float* __restrict__ Wo,  const float* __restrict__ bo,
                            float* __restrict__ out) {
    __shared__ float sW1[64 * 16];
    __shared__ float sb1[16];
    __shared__ float sW2[16 * 8];
    __shared__ float sb2[8];
    __shared__ float sWo[8];
    for (int i = threadIdx.x; i < 1024; i += blockDim.x) sW1[i] = Wd1[i];
    if (threadIdx.x < 16)  sb1[threadIdx.x] = bd1[threadIdx.x];
    if (threadIdx.x < 128) sW2[threadIdx.x] = Wd2[threadIdx.x];
    if (threadIdx.x < 8)   { sb2[threadIdx.x] = bd2[threadIdx.x]; sWo[threadIdx.x] = Wo[threadIdx.x]; }
    __syncthreads();
    int g = blockIdx.x * blockDim.x + threadIdx.x;
    if (g >= GG) return;
    const float* pr = d_scratch + OFF_POOL + g * 64;
    float h1[16];
#pragma unroll
    for (int k = 0; k < 16; k++) h1[k] = sb1[k];
    for (int f = 0; f < 64; f++) {
        float v = pr[f];
#pragma unroll
        for (int k = 0; k < 16; k++) h1[k] += v * sW1[f * 16 + k];
    }
#pragma unroll
    for (int k = 0; k < 16; k++) h1[k] = fmaxf(h1[k], 0.f);
    float h2[8];
#pragma unroll
    for (int m = 0; m < 8; m++) h2[m] = sb2[m];
#pragma unroll
    for (int k = 0; k < 16; k++) {
        float v = h1[k];
#pragma unroll
        for (int m = 0; m < 8; m++) h2[m] += v * sW2[k * 8 + m];
    }
    float z = bo[0];
#pragma unroll
    for (int m = 0; m < 8; m++) z += fmaxf(h2[m], 0.f) * sWo[m];
    out[g] = 1.f / (1.f + expf(-z));
}

// ---------------- launch ----------------
extern "C" void kernel_launch(void* const* d_in, const int* in_sizes, int n_in,
                              void* d_out, int out_size) {
    const float* x     = (const float*)d_in[0];
    const float* av    = (const float*)d_in[1];
    const float* ef    = (const float*)d_in[2];
    const int*   ei    = (const int*)  d_in[3];
    const int*   seg   = (const int*)  d_in[4];
    const float* Wg1   = (const float*)d_in[5];
    const float* bg1   = (const float*)d_in[6];
    const float* Wg2   = (const float*)d_in[7];
    const float* bg2   = (const float*)d_in[8];
    const float* We1   = (const float*)d_in[9];
    const float* be1   = (const float*)d_in[10];
    const float* root1 = (const float*)d_in[11];
    const float* bias1 = (const float*)d_in[12];
    const float* We2   = (const float*)d_in[13];
    const float* be2   = (const float*)d_in[14];
    const float* root2 = (const float*)d_in[15];
    const float* bias2 = (const float*)d_in[16];
    const float* Wd1   = (const float*)d_in[17];
    const float* bd1   = (const float*)d_in[18];
    const float* Wd2   = (const float*)d_in[19];
    const float* bd2   = (const float*)d_in[20];
    const float* Wo    = (const float*)d_in[21];
    const float* bo    = (const float*)d_in[22];
    float* out = (float*)d_out;

    constexpr int INIT_ITEMS = ZERO_COUNT / 4 + NN * 3;
    init_kernel<<<(INIT_ITEMS + 255) / 256, 256>>>(x);
    pass1_kernel<<<(EE * 3 + 383) / 384, 384>>>(ei, av, ef);
    post1_kernel<<<(NN + 127) / 128, 128>>>(Wg1, bg1, We1, be1, root1, bias1);
    pass2_kernel<<<(EE * 4 + 255) / 256, 256>>>(ei, av, ef);
    post2_kernel<<<(NN + 127) / 128, 128>>>(seg, Wg2, bg2, We2, be2, root2, bias2);
    head_kernel<<<2, 256>>>(Wd1, bd1, Wd2, bd2, Wo, bo, out);
}